// round 1
// baseline (speedup 1.0000x reference)
#include <cuda_runtime.h>
#include <cstddef>

#define N_NODES 16384
#define TM 128
#define KB 32
#define S_ADJ 130   // padded row stride (floats) for transposed adj tile; even -> 8B-aligned rows

// ---------------- scratch (device globals; no allocation allowed) ----------------
__device__ float g_xw[N_NODES * 64];        // holds H @ W (input to adj-GEMM)
__device__ float g_h [N_NODES * 64];        // holds relu(adj @ XW + b)
__device__ float g_partial[(N_NODES / TM) * 64];  // per-block column sums of layer-3 output

// ---------------- small feature GEMM: out[N,F] = in[N,KF] @ W[KF,F] ----------------
template<int KF, int F>
__global__ __launch_bounds__(256) void feat_gemm(const float* __restrict__ in,
                                                 const float* __restrict__ W,
                                                 float* __restrict__ out) {
    __shared__ float Ws[KF * F];
    for (int i = threadIdx.x; i < KF * F; i += 256) Ws[i] = W[i];
    __syncthreads();

    int idx = blockIdx.x * 256 + threadIdx.x;
    if (idx >= N_NODES * F) return;
    int f   = idx % F;
    int row = idx / F;
    const float4* xr = reinterpret_cast<const float4*>(in + (size_t)row * KF);
    float acc = 0.f;
#pragma unroll 4
    for (int k4 = 0; k4 < KF / 4; k4++) {
        float4 xv = xr[k4];
        int k = k4 * 4;
        acc += xv.x * Ws[(k + 0) * F + f];
        acc += xv.y * Ws[(k + 1) * F + f];
        acc += xv.z * Ws[(k + 2) * F + f];
        acc += xv.w * Ws[(k + 3) * F + f];
    }
    out[idx] = acc;
}

// ---------------- heavy GEMM: relu(adj[N,N] @ xw[N,F] + b) ----------------
// Block: 256 threads (tx = tid%16 -> column group, ty = tid/16 -> row group of 8).
// TM=128 rows per block, K streamed in KB=32 tiles.
// Accumulators are f32x2 (packed row pairs) -> FFMA2 at 2x FP32 rate.
template<int F, bool REDUCE>
__global__ __launch_bounds__(256) void adj_gemm(const float* __restrict__ adj,
                                                const float* __restrict__ xw,
                                                const float* __restrict__ bias,
                                                float* __restrict__ out,
                                                float* __restrict__ partial) {
    constexpr int TN = F / 16;
    __shared__ __align__(16) float adj_s[KB][S_ADJ];  // transposed: adj_s[k][r]
    __shared__ __align__(16) float x_s[KB][F];
    __shared__ float red_s[16][64];

    const int tid = threadIdx.x;
    const int tx = tid & 15;
    const int ty = tid >> 4;
    const int rowBase = blockIdx.x * TM;

    unsigned long long acc[4][TN];
#pragma unroll
    for (int p = 0; p < 4; p++)
#pragma unroll
        for (int j = 0; j < TN; j++) acc[p][j] = 0ull;

    float bval[TN];
#pragma unroll
    for (int j = 0; j < TN; j++) bval[j] = bias[tx * TN + j];

    for (int kt = 0; kt < N_NODES; kt += KB) {
        // load adj tile [TM x KB] transposed into adj_s (float4 global loads)
#pragma unroll
        for (int p = 0; p < 4; p++) {
            int lin  = tid + p * 256;        // 0..1023
            int kvec = lin & 7;              // 8 float4 per 32-wide row
            int r    = lin >> 3;             // 0..127
            float4 v = *reinterpret_cast<const float4*>(
                adj + (size_t)(rowBase + r) * N_NODES + kt + kvec * 4);
            adj_s[kvec * 4 + 0][r] = v.x;
            adj_s[kvec * 4 + 1][r] = v.y;
            adj_s[kvec * 4 + 2][r] = v.z;
            adj_s[kvec * 4 + 3][r] = v.w;
        }
        // load X tile [KB x F] (contiguous in gmem)
        const float4* xsrc = reinterpret_cast<const float4*>(xw + (size_t)kt * F);
#pragma unroll
        for (int lin = tid; lin < KB * F / 4; lin += 256)
            reinterpret_cast<float4*>(&x_s[0][0])[lin] = xsrc[lin];
        __syncthreads();

#pragma unroll
        for (int kk = 0; kk < KB; kk++) {
            unsigned long long a2[4];
#pragma unroll
            for (int p = 0; p < 4; p++)   // LDS.64: row pair (ty*8+2p, +1)
                a2[p] = *reinterpret_cast<const unsigned long long*>(&adj_s[kk][ty * 8 + 2 * p]);
#pragma unroll
            for (int j = 0; j < TN; j++) {
                unsigned xu = __float_as_uint(x_s[kk][tx * TN + j]);
                unsigned long long x2;
                asm("mov.b64 %0, {%1, %1};" : "=l"(x2) : "r"(xu));
#pragma unroll
                for (int p = 0; p < 4; p++)
                    asm("fma.rn.f32x2 %0, %1, %2, %3;"
                        : "=l"(acc[p][j]) : "l"(a2[p]), "l"(x2), "l"(acc[p][j]));
            }
        }
        __syncthreads();
    }

    // epilogue: bias + relu, then store or column-reduce
    float csum[TN];
#pragma unroll
    for (int j = 0; j < TN; j++) csum[j] = 0.f;

#pragma unroll
    for (int p = 0; p < 4; p++) {
#pragma unroll
        for (int j = 0; j < TN; j++) {
            float lo = __uint_as_float((unsigned)(acc[p][j] & 0xffffffffull));
            float hi = __uint_as_float((unsigned)(acc[p][j] >> 32));
            float v0 = fmaxf(lo + bval[j], 0.f);
            float v1 = fmaxf(hi + bval[j], 0.f);
            if constexpr (!REDUCE) {
                int r0 = rowBase + ty * 8 + 2 * p;
                out[(size_t)r0 * F + tx * TN + j]       = v0;
                out[(size_t)(r0 + 1) * F + tx * TN + j] = v1;
            } else {
                csum[j] += v0 + v1;
            }
        }
    }

    if constexpr (REDUCE) {
#pragma unroll
        for (int j = 0; j < TN; j++) red_s[ty][tx * TN + j] = csum[j];
        __syncthreads();
        if (ty == 0) {
#pragma unroll
            for (int j = 0; j < TN; j++) {
                int c = tx * TN + j;
                float s = 0.f;
#pragma unroll
                for (int t = 0; t < 16; t++) s += red_s[t][c];
                partial[blockIdx.x * 64 + c] = s;
            }
        }
    }
}

// ---------------- readout + MLP head + softmax ----------------
__global__ void head_kernel(const float* __restrict__ partial,
                            const float* __restrict__ fcW1, const float* __restrict__ fcb1,
                            const float* __restrict__ fcW2, const float* __restrict__ fcb2,
                            float* __restrict__ out) {
    __shared__ float mean_s[64];
    __shared__ float z1_s[32];
    int t = threadIdx.x;  // 64 threads
    float s = 0.f;
    for (int b = 0; b < N_NODES / TM; b++) s += partial[b * 64 + t];
    mean_s[t] = s * (1.0f / N_NODES);
    __syncthreads();
    if (t < 32) {
        float a = 0.f;
#pragma unroll
        for (int c = 0; c < 64; c++) a += mean_s[c] * fcW1[c * 32 + t];
        z1_s[t] = fmaxf(a + fcb1[t], 0.f);
    }
    __syncthreads();
    if (t == 0) {
        float z0 = fcb2[0], z1 = fcb2[1];
#pragma unroll
        for (int j = 0; j < 32; j++) {
            z0 += z1_s[j] * fcW2[j * 2 + 0];
            z1 += z1_s[j] * fcW2[j * 2 + 1];
        }
        float m  = fmaxf(z0, z1);
        float e0 = expf(z0 - m), e1 = expf(z1 - m);
        float inv = 1.0f / (e0 + e1);
        out[0] = e0 * inv;
        out[1] = e1 * inv;
    }
}

// ---------------- launch ----------------
extern "C" void kernel_launch(void* const* d_in, const int* in_sizes, int n_in,
                              void* d_out, int out_size) {
    const float* x    = (const float*)d_in[0];
    const float* adj  = (const float*)d_in[1];
    // d_in[2] = idx_map (unused by the reference)
    const float* W1   = (const float*)d_in[3];
    const float* b1   = (const float*)d_in[4];
    const float* W2   = (const float*)d_in[5];
    const float* b2   = (const float*)d_in[6];
    const float* W3   = (const float*)d_in[7];
    const float* b3   = (const float*)d_in[8];
    const float* fcW1 = (const float*)d_in[9];
    const float* fcb1 = (const float*)d_in[10];
    const float* fcW2 = (const float*)d_in[11];
    const float* fcb2 = (const float*)d_in[12];
    float* out = (float*)d_out;

    float *xw, *h, *partial;
    cudaGetSymbolAddress((void**)&xw, g_xw);
    cudaGetSymbolAddress((void**)&h, g_h);
    cudaGetSymbolAddress((void**)&partial, g_partial);

    feat_gemm<128, 32><<<(N_NODES * 32) / 256, 256>>>(x, W1, xw);
    adj_gemm<32, false><<<N_NODES / TM, 256>>>(adj, xw, b1, h, nullptr);
    feat_gemm<32, 48><<<(N_NODES * 48) / 256, 256>>>(h, W2, xw);
    adj_gemm<48, false><<<N_NODES / TM, 256>>>(adj, xw, b2, h, nullptr);
    feat_gemm<48, 64><<<(N_NODES * 64) / 256, 256>>>(h, W3, xw);
    adj_gemm<64, true><<<N_NODES / TM, 256>>>(adj, xw, b3, nullptr, partial);
    head_kernel<<<1, 64>>>(partial, fcW1, fcb1, fcW2, fcb2, out);
}

// round 3
// speedup vs baseline: 2.9600x; 2.9600x over previous
#include <cuda_runtime.h>
#include <cstdint>
#include <cstddef>

#define N_NODES 16384
#define BM 128
#define BK 32
#define SPLITK 8
#define KSPAN (N_NODES / SPLITK)   // 2048
#define NKT (KSPAN / BK)           // 64 k-tiles per block
#define SA 36                      // padded smem row stride (words)

// ---------------- scratch (device globals; no allocation allowed) ----------------
__device__ float g_xw[N_NODES * 64];                 // H @ W, row-major [N,F]
__device__ float g_h [N_NODES * 64];                 // relu(adj @ XW + b), row-major [N,F]
__device__ float g_part[SPLITK * N_NODES * 64];      // split-K partials [sk][N][F]
__device__ float g_colsum[256 * 64];                 // per-block column sums (layer 3)

// ---------------- helpers ----------------
__device__ __forceinline__ uint32_t f2tf(float x) {   // round-to-nearest TF32
    uint32_t u; asm("cvt.rna.tf32.f32 %0, %1;" : "=r"(u) : "f"(x)); return u;
}
__device__ __forceinline__ void mma8(float* c,
                                     uint32_t a0, uint32_t a1, uint32_t a2, uint32_t a3,
                                     uint32_t b0, uint32_t b1) {
    asm volatile("mma.sync.aligned.m16n8k8.row.col.f32.tf32.tf32.f32 "
                 "{%0,%1,%2,%3}, {%4,%5,%6,%7}, {%8,%9}, {%0,%1,%2,%3};"
                 : "+f"(c[0]), "+f"(c[1]), "+f"(c[2]), "+f"(c[3])
                 : "r"(a0), "r"(a1), "r"(a2), "r"(a3), "r"(b0), "r"(b1));
}

// ---------------- small feature GEMM: out[N,F] = in[N,KF] @ W[KF,F] (row-major out) ----------------
template<int KF, int F>
__global__ __launch_bounds__(256) void feat_gemm(const float* __restrict__ in,
                                                 const float* __restrict__ W,
                                                 float* __restrict__ out) {
    __shared__ float Ws[KF * F];
    for (int i = threadIdx.x; i < KF * F; i += 256) Ws[i] = W[i];
    __syncthreads();

    int idx = blockIdx.x * 256 + threadIdx.x;
    if (idx >= N_NODES * F) return;
    int f   = idx % F;
    int row = idx / F;
    const float4* xr = reinterpret_cast<const float4*>(in + (size_t)row * KF);
    float acc = 0.f;
#pragma unroll 4
    for (int k4 = 0; k4 < KF / 4; k4++) {
        float4 xv = xr[k4];
        int k = k4 * 4;
        acc += xv.x * Ws[(k + 0) * F + f];
        acc += xv.y * Ws[(k + 1) * F + f];
        acc += xv.z * Ws[(k + 2) * F + f];
        acc += xv.w * Ws[(k + 3) * F + f];
    }
    out[idx] = acc;
}

// ---------------- split-K TF32 mma.sync GEMM: part[sk] = adj[rows, kspan] @ xw[kspan, F] ----------------
// Block: 256 threads / 8 warps. Warp tile: m32 x n(F/2). K-tile = 32.
// Smem layout column-permuted (col' = (k&3)*8 + (k>>2)) so all fragment loads are LDS.128.
template<int F>
__global__ __launch_bounds__(256) void adj_gemm_mma(const float* __restrict__ adj,
                                                    const float* __restrict__ xw,
                                                    float* __restrict__ part) {
    constexpr int F2  = F / 2;
    constexpr int NF2 = F2 / 8;                // n-fragments per warp
    constexpr int BQ  = (8 * F + 255) / 256;   // B float4 loads per thread

    __shared__ __align__(16) uint32_t As[BM * SA];
    __shared__ __align__(16) uint32_t Bs[F * SA];

    const int tid  = threadIdx.x;
    const int wid  = tid >> 5, lane = tid & 31;
    const int g    = lane >> 2, t = lane & 3;
    const int wx   = wid >> 1,  wy = wid & 1;
    const int rowBase = blockIdx.x * BM;
    const int k0      = blockIdx.y * KSPAN;

    float c[2][NF2][4];
#pragma unroll
    for (int mf = 0; mf < 2; mf++)
#pragma unroll
        for (int nf = 0; nf < NF2; nf++)
#pragma unroll
            for (int e = 0; e < 4; e++) c[mf][nf][e] = 0.f;

    // ---- per-thread staging maps ----
    int ar[4], aj[4];
    const float* ap[4];
#pragma unroll
    for (int i = 0; i < 4; i++) {
        int lin = tid + 256 * i;           // 0..1023 -> 128 rows x 8 float4
        ar[i] = lin >> 3;
        aj[i] = lin & 7;
        ap[i] = adj + (size_t)(rowBase + ar[i]) * N_NODES + k0 + 4 * aj[i];
    }
    int bk[BQ], bf[BQ]; bool bon[BQ];
    const float* bp[BQ];
#pragma unroll
    for (int q = 0; q < BQ; q++) {
        int lin = tid + 256 * q;           // 32 rows x (F/4) float4 = 8F units
        bon[q] = (lin < 8 * F);
        int l  = bon[q] ? lin : 0;
        bk[q] = l / (F / 4);
        bf[q] = l % (F / 4);
        bp[q] = xw + (size_t)(k0 + bk[q]) * F + 4 * bf[q];
    }

    float4 rA[4], rB[BQ];
    // prologue: tile 0
#pragma unroll
    for (int i = 0; i < 4; i++) rA[i] = *reinterpret_cast<const float4*>(ap[i]);
#pragma unroll
    for (int q = 0; q < BQ; q++) if (bon[q]) rB[q] = *reinterpret_cast<const float4*>(bp[q]);

    // store tile 0
#pragma unroll
    for (int i = 0; i < 4; i++) {
        uint32_t* d = &As[ar[i] * SA + aj[i]];
        d[0]  = f2tf(rA[i].x); d[8]  = f2tf(rA[i].y);
        d[16] = f2tf(rA[i].z); d[24] = f2tf(rA[i].w);
    }
#pragma unroll
    for (int q = 0; q < BQ; q++) if (bon[q]) {
        int colp = (bk[q] & 3) * 8 + (bk[q] >> 2);
        uint32_t* d = &Bs[(4 * bf[q]) * SA + colp];
        d[0]      = f2tf(rB[q].x); d[SA]     = f2tf(rB[q].y);
        d[2 * SA] = f2tf(rB[q].z); d[3 * SA] = f2tf(rB[q].w);
    }
    __syncthreads();

#pragma unroll 1
    for (int ti = 0; ti < NKT; ti++) {
        const bool has = (ti + 1 < NKT);
        const int  kt  = (ti + 1) * BK;
        // prefetch next tile into regs (hidden under HMMA below)
        if (has) {
#pragma unroll
            for (int i = 0; i < 4; i++) rA[i] = *reinterpret_cast<const float4*>(ap[i] + kt);
#pragma unroll
            for (int q = 0; q < BQ; q++) if (bon[q])
                rB[q] = *reinterpret_cast<const float4*>(bp[q] + (size_t)kt * F);
        }
        // compute current tile from smem
#pragma unroll
        for (int mf = 0; mf < 2; mf++) {
            const int r0 = wx * 32 + mf * 16 + g;
            uint32_t alo[8], ahi[8];
            *reinterpret_cast<uint4*>(&alo[0]) = *reinterpret_cast<const uint4*>(&As[r0 * SA + 8 * t]);
            *reinterpret_cast<uint4*>(&alo[4]) = *reinterpret_cast<const uint4*>(&As[r0 * SA + 8 * t + 4]);
            *reinterpret_cast<uint4*>(&ahi[0]) = *reinterpret_cast<const uint4*>(&As[(r0 + 8) * SA + 8 * t]);
            *reinterpret_cast<uint4*>(&ahi[4]) = *reinterpret_cast<const uint4*>(&As[(r0 + 8) * SA + 8 * t + 4]);
#pragma unroll
            for (int nf = 0; nf < NF2; nf++) {
                const int n = wy * F2 + nf * 8 + g;
                uint32_t bb[8];
                *reinterpret_cast<uint4*>(&bb[0]) = *reinterpret_cast<const uint4*>(&Bs[n * SA + 8 * t]);
                *reinterpret_cast<uint4*>(&bb[4]) = *reinterpret_cast<const uint4*>(&Bs[n * SA + 8 * t + 4]);
#pragma unroll
                for (int ks = 0; ks < 4; ks++)
                    mma8(c[mf][nf], alo[2 * ks], ahi[2 * ks], alo[2 * ks + 1], ahi[2 * ks + 1],
                         bb[2 * ks], bb[2 * ks + 1]);
            }
        }
        __syncthreads();
        if (has) {
#pragma unroll
            for (int i = 0; i < 4; i++) {
                uint32_t* d = &As[ar[i] * SA + aj[i]];
                d[0]  = f2tf(rA[i].x); d[8]  = f2tf(rA[i].y);
                d[16] = f2tf(rA[i].z); d[24] = f2tf(rA[i].w);
            }
#pragma unroll
            for (int q = 0; q < BQ; q++) if (bon[q]) {
                int colp = (bk[q] & 3) * 8 + (bk[q] >> 2);
                uint32_t* d = &Bs[(4 * bf[q]) * SA + colp];
                d[0]      = f2tf(rB[q].x); d[SA]     = f2tf(rB[q].y);
                d[2 * SA] = f2tf(rB[q].z); d[3 * SA] = f2tf(rB[q].w);
            }
            __syncthreads();
        }
    }

    // ---- store partials ----
    float* pbase = part + (size_t)blockIdx.y * N_NODES * F;
#pragma unroll
    for (int mf = 0; mf < 2; mf++) {
        const int r0 = rowBase + wx * 32 + mf * 16 + g;
#pragma unroll
        for (int nf = 0; nf < NF2; nf++) {
            const int col = wy * F2 + nf * 8 + 2 * t;
            *reinterpret_cast<float2*>(pbase + (size_t)r0 * F + col) =
                make_float2(c[mf][nf][0], c[mf][nf][1]);
            *reinterpret_cast<float2*>(pbase + (size_t)(r0 + 8) * F + col) =
                make_float2(c[mf][nf][2], c[mf][nf][3]);
        }
    }
}

// ---------------- combine split-K partials: h = relu(sum_sk part + b) ----------------
template<int F>
__global__ __launch_bounds__(256) void combine_h(const float* __restrict__ part,
                                                 const float* __restrict__ bias,
                                                 float* __restrict__ h) {
    int idx = blockIdx.x * 256 + threadIdx.x;          // float4 index
    if (idx >= N_NODES * F / 4) return;
    float4 s = make_float4(0.f, 0.f, 0.f, 0.f);
#pragma unroll
    for (int sk = 0; sk < SPLITK; sk++) {
        float4 v = reinterpret_cast<const float4*>(part)[(size_t)sk * (N_NODES * F / 4) + idx];
        s.x += v.x; s.y += v.y; s.z += v.z; s.w += v.w;
    }
    int f = (idx * 4) % F;
    s.x = fmaxf(s.x + bias[f + 0], 0.f);
    s.y = fmaxf(s.y + bias[f + 1], 0.f);
    s.z = fmaxf(s.z + bias[f + 2], 0.f);
    s.w = fmaxf(s.w + bias[f + 3], 0.f);
    reinterpret_cast<float4*>(h)[idx] = s;
}

// ---------------- layer-3 combine + deterministic column reduction (F=64) ----------------
__global__ __launch_bounds__(256) void combine_reduce(const float* __restrict__ part,
                                                      const float* __restrict__ bias,
                                                      float* __restrict__ colsum) {
    __shared__ float red[4][64];
    const int tid = threadIdx.x;
    const int c = tid & 63, rg = tid >> 6;
    const int rowBase = blockIdx.x * 64;
    const float b = bias[c];
    float s = 0.f;
#pragma unroll 4
    for (int i = 0; i < 16; i++) {
        const int row = rowBase + rg + 4 * i;
        float v = 0.f;
#pragma unroll
        for (int sk = 0; sk < SPLITK; sk++)
            v += part[((size_t)sk * N_NODES + row) * 64 + c];
        s += fmaxf(v + b, 0.f);
    }
    red[rg][c] = s;
    __syncthreads();
    if (rg == 0)
        colsum[blockIdx.x * 64 + c] = red[0][c] + red[1][c] + red[2][c] + red[3][c];
}

// ---------------- readout + MLP head + softmax ----------------
__global__ void head_kernel(const float* __restrict__ colsum,
                            const float* __restrict__ fcW1, const float* __restrict__ fcb1,
                            const float* __restrict__ fcW2, const float* __restrict__ fcb2,
                            float* __restrict__ out) {
    __shared__ float mean_s[64];
    __shared__ float z1_s[32];
    int t = threadIdx.x;  // 64 threads
    float s = 0.f;
    for (int bkl = 0; bkl < 256; bkl++) s += colsum[bkl * 64 + t];
    mean_s[t] = s * (1.0f / N_NODES);
    __syncthreads();
    if (t < 32) {
        float a = 0.f;
#pragma unroll
        for (int c = 0; c < 64; c++) a += mean_s[c] * fcW1[c * 32 + t];
        z1_s[t] = fmaxf(a + fcb1[t], 0.f);
    }
    __syncthreads();
    if (t == 0) {
        float z0 = fcb2[0], z1 = fcb2[1];
#pragma unroll
        for (int j = 0; j < 32; j++) {
            z0 += z1_s[j] * fcW2[j * 2 + 0];
            z1 += z1_s[j] * fcW2[j * 2 + 1];
        }
        float m  = fmaxf(z0, z1);
        float e0 = expf(z0 - m), e1 = expf(z1 - m);
        float inv = 1.0f / (e0 + e1);
        out[0] = e0 * inv;
        out[1] = e1 * inv;
    }
}

// ---------------- launch ----------------
extern "C" void kernel_launch(void* const* d_in, const int* in_sizes, int n_in,
                              void* d_out, int out_size) {
    const float* x    = (const float*)d_in[0];
    const float* adj  = (const float*)d_in[1];
    // d_in[2] = idx_map (unused by the reference)
    const float* W1   = (const float*)d_in[3];
    const float* b1   = (const float*)d_in[4];
    const float* W2   = (const float*)d_in[5];
    const float* b2   = (const float*)d_in[6];
    const float* W3   = (const float*)d_in[7];
    const float* b3   = (const float*)d_in[8];
    const float* fcW1 = (const float*)d_in[9];
    const float* fcb1 = (const float*)d_in[10];
    const float* fcW2 = (const float*)d_in[11];
    const float* fcb2 = (const float*)d_in[12];
    float* out = (float*)d_out;

    float *xw, *h, *part, *colsum;
    cudaGetSymbolAddress((void**)&xw, g_xw);
    cudaGetSymbolAddress((void**)&h, g_h);
    cudaGetSymbolAddress((void**)&part, g_part);
    cudaGetSymbolAddress((void**)&colsum, g_colsum);

    dim3 agrid(N_NODES / BM, SPLITK);

    feat_gemm<128, 32><<<(N_NODES * 32) / 256, 256>>>(x, W1, xw);
    adj_gemm_mma<32><<<agrid, 256>>>(adj, xw, part);
    combine_h<32><<<(N_NODES * 32 / 4 + 255) / 256, 256>>>(part, b1, h);

    feat_gemm<32, 48><<<(N_NODES * 48) / 256, 256>>>(h, W2, xw);
    adj_gemm_mma<48><<<agrid, 256>>>(adj, xw, part);
    combine_h<48><<<(N_NODES * 48 / 4 + 255) / 256, 256>>>(part, b2, h);

    feat_gemm<48, 64><<<(N_NODES * 64) / 256, 256>>>(h, W3, xw);
    adj_gemm_mma<64><<<agrid, 256>>>(adj, xw, part);
    combine_reduce<<<256, 256>>>(part, b3, colsum);

    head_kernel<<<1, 64>>>(colsum, fcW1, fcb1, fcW2, fcb2, out);
}

// round 4
// speedup vs baseline: 4.3619x; 1.4736x over previous
#include <cuda_runtime.h>
#include <cuda_bf16.h>
#include <cstdint>
#include <cstddef>

#define N_NODES 16384
#define BM 128
#define BK 32
#define SPLITK 8
#define KSPAN (N_NODES / SPLITK)   // 2048
#define NKT (KSPAN / BK)           // 64 k-tiles per CTA

// ---------------- scratch (device globals; no allocation allowed) ----------------
__device__ __nv_bfloat16 g_adj16[(size_t)N_NODES * N_NODES];  // 512MB bf16 adj copy
__device__ float    g_xw  [N_NODES * 64];                     // H @ W fp32, [k][F]
__device__ uint32_t g_xwT [64 * (N_NODES / 2)];               // (H@W)^T bf16 pairs, [f][kpair]
__device__ float    g_h   [N_NODES * 64];                     // relu layer out, [N][F]
__device__ float    g_part[SPLITK * N_NODES * 64];            // split-K partials
__device__ float    g_colsum[256 * 64];                       // layer-3 column sums

// ---------------- helpers ----------------
__device__ __forceinline__ uint32_t pack_bf16(float lo, float hi) {  // RN, lo in low 16 bits
    uint32_t r; asm("cvt.rn.bf16x2.f32 %0, %1, %2;" : "=r"(r) : "f"(hi), "f"(lo)); return r;
}
__device__ __forceinline__ void mma16(float* c,
                                      uint32_t a0, uint32_t a1, uint32_t a2, uint32_t a3,
                                      uint32_t b0, uint32_t b1) {
    asm volatile("mma.sync.aligned.m16n8k16.row.col.f32.bf16.bf16.f32 "
                 "{%0,%1,%2,%3}, {%4,%5,%6,%7}, {%8,%9}, {%0,%1,%2,%3};"
                 : "+f"(c[0]), "+f"(c[1]), "+f"(c[2]), "+f"(c[3])
                 : "r"(a0), "r"(a1), "r"(a2), "r"(a3), "r"(b0), "r"(b1));
}
// pair-permuted column: pair p (0..15) -> col ((p&3)<<2)|(p>>2); then xor-swizzle by row
__device__ __forceinline__ int swz(int row, int col) { return row * 16 + (col ^ ((row & 3) << 2)); }

// ---------------- small feature GEMM: g_xw[k][F] = in[N,KF] @ W[KF,F] ----------------
template<int KF, int F>
__global__ __launch_bounds__(256) void feat_gemm(const float* __restrict__ in,
                                                 const float* __restrict__ W,
                                                 float* __restrict__ out) {
    __shared__ float Ws[KF * F];
    for (int i = threadIdx.x; i < KF * F; i += 256) Ws[i] = W[i];
    __syncthreads();
    int idx = blockIdx.x * 256 + threadIdx.x;
    if (idx >= N_NODES * F) return;
    int f = idx % F, row = idx / F;
    const float4* xr = reinterpret_cast<const float4*>(in + (size_t)row * KF);
    float acc = 0.f;
#pragma unroll 4
    for (int k4 = 0; k4 < KF / 4; k4++) {
        float4 xv = xr[k4];
        int k = k4 * 4;
        acc += xv.x * Ws[(k + 0) * F + f];
        acc += xv.y * Ws[(k + 1) * F + f];
        acc += xv.z * Ws[(k + 2) * F + f];
        acc += xv.w * Ws[(k + 3) * F + f];
    }
    out[idx] = acc;
}

// ---------------- transpose + bf16-pack: g_xwT[f][kpair] from g_xw[k][F] ----------------
template<int F>
__global__ __launch_bounds__(256) void xpose(const float* __restrict__ in,
                                             uint32_t* __restrict__ outT) {
    __shared__ float tile[64 * (F + 1)];
    const int tid = threadIdx.x;
    const int kb = blockIdx.x * 64;
#pragma unroll
    for (int i = 0; i < F / 16; i++) {
        int lin = tid + 256 * i;                    // float4 index within 64xF block
        float4 v = reinterpret_cast<const float4*>(in + (size_t)kb * F)[lin];
        int k = (lin * 4) / F, f = (lin * 4) % F;
        tile[k * (F + 1) + f + 0] = v.x; tile[k * (F + 1) + f + 1] = v.y;
        tile[k * (F + 1) + f + 2] = v.z; tile[k * (F + 1) + f + 3] = v.w;
    }
    __syncthreads();
#pragma unroll
    for (int w = 0; w < F / 8; w++) {
        int lin = tid + 256 * w;
        int f = lin >> 5, j = lin & 31;
        outT[(size_t)f * (N_NODES / 2) + kb / 2 + j] =
            pack_bf16(tile[(2 * j) * (F + 1) + f], tile[(2 * j + 1) * (F + 1) + f]);
    }
}

// ---------------- split-K bf16 mma GEMM: part[sk] = adj @ xw  ----------------
// CVT=true: read fp32 adj, RN-convert, also write g_adj16. CVT=false: read g_adj16.
template<int F, bool CVT>
__global__ __launch_bounds__(256) void adj_gemm_bf(const float* __restrict__ adj,
                                                   float* __restrict__ part) {
    constexpr int F2 = F / 2, NF2 = F2 / 8;
    __shared__ __align__(16) uint32_t As[2][BM * 16];
    __shared__ __align__(16) uint32_t Bs[2][F * 16];

    const int tid = threadIdx.x;
    const int wid = tid >> 5, lane = tid & 31;
    const int g = lane >> 2, t = lane & 3;
    const int wx = wid >> 1, wy = wid & 1;
    const int rowBase = blockIdx.x * BM;
    const int k0 = blockIdx.y * KSPAN;

    float c[2][NF2][4];
#pragma unroll
    for (int mf = 0; mf < 2; mf++)
#pragma unroll
        for (int nf = 0; nf < NF2; nf++)
#pragma unroll
            for (int e = 0; e < 4; e++) c[mf][nf][e] = 0.f;

    // ---- staging maps ----
    // CVT path: 4 fp32 float4 chunks per thread (128 rows x 8 chunks)
    int c_row[4], c_j[4];
    const float* c_src[4];
    __nv_bfloat16* c_dst[4];
    // fast path: 2 bf16 uint4 chunks per thread (128 rows x 4 chunks)
    int f_row[2], f_jc[2];
    const uint4* f_src[2];
    if (CVT) {
#pragma unroll
        for (int i = 0; i < 4; i++) {
            int lin = tid + 256 * i;
            c_row[i] = lin >> 3; c_j[i] = lin & 7;
            c_src[i] = adj + (size_t)(rowBase + c_row[i]) * N_NODES + k0 + 4 * c_j[i];
            c_dst[i] = g_adj16 + (size_t)(rowBase + c_row[i]) * N_NODES + k0 + 4 * c_j[i];
        }
    } else {
#pragma unroll
        for (int i = 0; i < 2; i++) {
            int lin = tid + 256 * i;
            f_row[i] = lin >> 2; f_jc[i] = lin & 3;
            f_src[i] = reinterpret_cast<const uint4*>(
                g_adj16 + (size_t)(rowBase + f_row[i]) * N_NODES + k0 + 8 * f_jc[i]);
        }
    }
    // B: one uint4 (4 k-pairs) per thread from g_xwT
    const bool bon = tid < 4 * F;
    const int b_f = tid >> 2, b_jc = tid & 3;
    const uint4* b_src = reinterpret_cast<const uint4*>(
        g_xwT + (size_t)(bon ? b_f : 0) * (N_NODES / 2) + k0 / 2 + 4 * b_jc);

    float4 rAc[4];
    uint4  rAf[2], rB;
    // ---- prologue: load tile 0 ----
    if (CVT) {
#pragma unroll
        for (int i = 0; i < 4; i++) rAc[i] = *reinterpret_cast<const float4*>(c_src[i]);
    } else {
#pragma unroll
        for (int i = 0; i < 2; i++) rAf[i] = f_src[i][0];
    }
    if (bon) rB = b_src[0];

#pragma unroll 1
    for (int ti = 0; ti < NKT; ti++) {
        const int buf = ti & 1;
        // ---- stage tile ti from regs into smem (and bf16 copy to gmem on CVT) ----
        if (CVT) {
#pragma unroll
            for (int i = 0; i < 4; i++) {
                uint32_t p0 = pack_bf16(rAc[i].x, rAc[i].y);
                uint32_t p1 = pack_bf16(rAc[i].z, rAc[i].w);
                int pe = 2 * c_j[i], po = pe + 1;
                As[buf][swz(c_row[i], ((pe & 3) << 2) | (pe >> 2))] = p0;
                As[buf][swz(c_row[i], ((po & 3) << 2) | (po >> 2))] = p1;
                *reinterpret_cast<uint2*>(c_dst[i] + (size_t)ti * BK) = make_uint2(p0, p1);
            }
        } else {
#pragma unroll
            for (int i = 0; i < 2; i++) {
                As[buf][swz(f_row[i], (0 << 2) | f_jc[i])] = rAf[i].x;
                As[buf][swz(f_row[i], (1 << 2) | f_jc[i])] = rAf[i].y;
                As[buf][swz(f_row[i], (2 << 2) | f_jc[i])] = rAf[i].z;
                As[buf][swz(f_row[i], (3 << 2) | f_jc[i])] = rAf[i].w;
            }
        }
        if (bon) {
            Bs[buf][swz(b_f, (0 << 2) | b_jc)] = rB.x;
            Bs[buf][swz(b_f, (1 << 2) | b_jc)] = rB.y;
            Bs[buf][swz(b_f, (2 << 2) | b_jc)] = rB.z;
            Bs[buf][swz(b_f, (3 << 2) | b_jc)] = rB.w;
        }
        // ---- prefetch tile ti+1 (completes under compute) ----
        if (ti + 1 < NKT) {
            if (CVT) {
#pragma unroll
                for (int i = 0; i < 4; i++)
                    rAc[i] = *reinterpret_cast<const float4*>(c_src[i] + (size_t)(ti + 1) * BK);
            } else {
#pragma unroll
                for (int i = 0; i < 2; i++)
                    rAf[i] = *reinterpret_cast<const uint4*>(
                        reinterpret_cast<const __nv_bfloat16*>(f_src[i]) + (size_t)(ti + 1) * BK);
            }
            if (bon) rB = *reinterpret_cast<const uint4*>(
                reinterpret_cast<const uint32_t*>(b_src) + (ti + 1) * (BK / 2));
        }
        __syncthreads();
        // ---- compute tile ti ----
#pragma unroll
        for (int mf = 0; mf < 2; mf++) {
            const int r0 = wx * 32 + mf * 16 + g;
            uint4 Alo = *reinterpret_cast<const uint4*>(&As[buf][swz(r0, 4 * t)]);
            uint4 Ahi = *reinterpret_cast<const uint4*>(&As[buf][swz(r0 + 8, 4 * t)]);
#pragma unroll
            for (int nf = 0; nf < NF2; nf++) {
                const int n = wy * F2 + nf * 8 + g;
                uint4 Bv = *reinterpret_cast<const uint4*>(&Bs[buf][swz(n, 4 * t)]);
                mma16(c[mf][nf], Alo.x, Ahi.x, Alo.y, Ahi.y, Bv.x, Bv.y);
                mma16(c[mf][nf], Alo.z, Ahi.z, Alo.w, Ahi.w, Bv.z, Bv.w);
            }
        }
    }

    // ---- store partials ----
    float* pbase = part + (size_t)blockIdx.y * N_NODES * F;
#pragma unroll
    for (int mf = 0; mf < 2; mf++) {
        const int r0 = rowBase + wx * 32 + mf * 16 + g;
#pragma unroll
        for (int nf = 0; nf < NF2; nf++) {
            const int col = wy * F2 + nf * 8 + 2 * t;
            *reinterpret_cast<float2*>(pbase + (size_t)r0 * F + col) =
                make_float2(c[mf][nf][0], c[mf][nf][1]);
            *reinterpret_cast<float2*>(pbase + (size_t)(r0 + 8) * F + col) =
                make_float2(c[mf][nf][2], c[mf][nf][3]);
        }
    }
}

// ---------------- combine split-K partials: h = relu(sum_sk part + b) ----------------
template<int F>
__global__ __launch_bounds__(256) void combine_h(const float* __restrict__ part,
                                                 const float* __restrict__ bias,
                                                 float* __restrict__ h) {
    int idx = blockIdx.x * 256 + threadIdx.x;
    if (idx >= N_NODES * F / 4) return;
    float4 s = make_float4(0.f, 0.f, 0.f, 0.f);
#pragma unroll
    for (int sk = 0; sk < SPLITK; sk++) {
        float4 v = reinterpret_cast<const float4*>(part)[(size_t)sk * (N_NODES * F / 4) + idx];
        s.x += v.x; s.y += v.y; s.z += v.z; s.w += v.w;
    }
    int f = (idx * 4) % F;
    s.x = fmaxf(s.x + bias[f + 0], 0.f);
    s.y = fmaxf(s.y + bias[f + 1], 0.f);
    s.z = fmaxf(s.z + bias[f + 2], 0.f);
    s.w = fmaxf(s.w + bias[f + 3], 0.f);
    reinterpret_cast<float4*>(h)[idx] = s;
}

// ---------------- layer-3 combine + deterministic column reduction (F=64) ----------------
__global__ __launch_bounds__(256) void combine_reduce(const float* __restrict__ part,
                                                      const float* __restrict__ bias,
                                                      float* __restrict__ colsum) {
    __shared__ float red[4][64];
    const int tid = threadIdx.x;
    const int c = tid & 63, rg = tid >> 6;
    const int rowBase = blockIdx.x * 64;
    const float b = bias[c];
    float s = 0.f;
#pragma unroll 4
    for (int i = 0; i < 16; i++) {
        const int row = rowBase + rg + 4 * i;
        float v = 0.f;
#pragma unroll
        for (int sk = 0; sk < SPLITK; sk++)
            v += part[((size_t)sk * N_NODES + row) * 64 + c];
        s += fmaxf(v + b, 0.f);
    }
    red[rg][c] = s;
    __syncthreads();
    if (rg == 0)
        colsum[blockIdx.x * 64 + c] = red[0][c] + red[1][c] + red[2][c] + red[3][c];
}

// ---------------- readout + MLP head + softmax ----------------
__global__ void head_kernel(const float* __restrict__ colsum,
                            const float* __restrict__ fcW1, const float* __restrict__ fcb1,
                            const float* __restrict__ fcW2, const float* __restrict__ fcb2,
                            float* __restrict__ out) {
    __shared__ float mean_s[64];
    __shared__ float z1_s[32];
    int t = threadIdx.x;  // 64 threads
    float s = 0.f;
    for (int b = 0; b < 256; b++) s += colsum[b * 64 + t];
    mean_s[t] = s * (1.0f / N_NODES);
    __syncthreads();
    if (t < 32) {
        float a = 0.f;
#pragma unroll
        for (int c = 0; c < 64; c++) a += mean_s[c] * fcW1[c * 32 + t];
        z1_s[t] = fmaxf(a + fcb1[t], 0.f);
    }
    __syncthreads();
    if (t == 0) {
        float z0 = fcb2[0], z1 = fcb2[1];
#pragma unroll
        for (int j = 0; j < 32; j++) {
            z0 += z1_s[j] * fcW2[j * 2 + 0];
            z1 += z1_s[j] * fcW2[j * 2 + 1];
        }
        float m  = fmaxf(z0, z1);
        float e0 = expf(z0 - m), e1 = expf(z1 - m);
        float inv = 1.0f / (e0 + e1);
        out[0] = e0 * inv;
        out[1] = e1 * inv;
    }
}

// ---------------- launch ----------------
extern "C" void kernel_launch(void* const* d_in, const int* in_sizes, int n_in,
                              void* d_out, int out_size) {
    const float* x    = (const float*)d_in[0];
    const float* adj  = (const float*)d_in[1];
    // d_in[2] = idx_map (unused by the reference)
    const float* W1   = (const float*)d_in[3];
    const float* b1   = (const float*)d_in[4];
    const float* W2   = (const float*)d_in[5];
    const float* b2   = (const float*)d_in[6];
    const float* W3   = (const float*)d_in[7];
    const float* b3   = (const float*)d_in[8];
    const float* fcW1 = (const float*)d_in[9];
    const float* fcb1 = (const float*)d_in[10];
    const float* fcW2 = (const float*)d_in[11];
    const float* fcb2 = (const float*)d_in[12];
    float* out = (float*)d_out;

    float *xw, *h, *part, *colsum;
    uint32_t* xwT;
    cudaGetSymbolAddress((void**)&xw, g_xw);
    cudaGetSymbolAddress((void**)&xwT, g_xwT);
    cudaGetSymbolAddress((void**)&h, g_h);
    cudaGetSymbolAddress((void**)&part, g_part);
    cudaGetSymbolAddress((void**)&colsum, g_colsum);

    dim3 agrid(N_NODES / BM, SPLITK);

    feat_gemm<128, 32><<<(N_NODES * 32) / 256, 256>>>(x, W1, xw);
    xpose<32><<<N_NODES / 64, 256>>>(xw, xwT);
    adj_gemm_bf<32, true><<<agrid, 256>>>(adj, part);
    combine_h<32><<<(N_NODES * 32 / 4 + 255) / 256, 256>>>(part, b1, h);

    feat_gemm<32, 48><<<(N_NODES * 48) / 256, 256>>>(h, W2, xw);
    xpose<48><<<N_NODES / 64, 256>>>(xw, xwT);
    adj_gemm_bf<48, false><<<agrid, 256>>>(nullptr, part);
    combine_h<48><<<(N_NODES * 48 / 4 + 255) / 256, 256>>>(part, b2, h);

    feat_gemm<48, 64><<<(N_NODES * 64) / 256, 256>>>(h, W3, xw);
    xpose<64><<<N_NODES / 64, 256>>>(xw, xwT);
    adj_gemm_bf<64, false><<<agrid, 256>>>(nullptr, part);
    combine_reduce<<<256, 256>>>(part, b3, colsum);

    head_kernel<<<1, 64>>>(colsum, fcW1, fcb1, fcW2, fcb2, out);
}

// round 5
// speedup vs baseline: 5.0785x; 1.1643x over previous
#include <cuda_runtime.h>
#include <cuda_bf16.h>
#include <cstdint>
#include <cstddef>

#define N_NODES 16384
#define BM 128
#define BK 32
#define SPLITK 8
#define KSPAN (N_NODES / SPLITK)   // 2048
#define NKT (KSPAN / BK)           // 64 k-tiles per CTA

// ---------------- scratch (device globals; no allocation allowed) ----------------
__device__ __nv_bfloat16 g_adj16[(size_t)N_NODES * N_NODES];  // 512MB bf16 adj copy
__device__ float    g_xw  [N_NODES * 64];                     // H @ W fp32, [k][F]
__device__ uint32_t g_xwT [64 * (N_NODES / 2)];               // (H@W)^T bf16 pairs, [f][kpair]
__device__ float    g_h   [N_NODES * 64];                     // relu layer out, [N][F]
__device__ float    g_part[SPLITK * N_NODES * 64];            // split-K partials
__device__ float    g_colsum[256 * 64];                       // layer-3 column sums

// ---------------- helpers ----------------
__device__ __forceinline__ uint32_t smem_u32(const void* p) {
    uint32_t a;
    asm("{ .reg .u64 t; cvta.to.shared.u64 t, %1; cvt.u32.u64 %0, t; }" : "=r"(a) : "l"(p));
    return a;
}
__device__ __forceinline__ uint32_t pack_bf16(float lo, float hi) {  // RN, lo in low 16 bits
    uint32_t r; asm("cvt.rn.bf16x2.f32 %0, %1, %2;" : "=r"(r) : "f"(hi), "f"(lo)); return r;
}
__device__ __forceinline__ void mma16(float* c,
                                      uint32_t a0, uint32_t a1, uint32_t a2, uint32_t a3,
                                      uint32_t b0, uint32_t b1) {
    asm volatile("mma.sync.aligned.m16n8k16.row.col.f32.bf16.bf16.f32 "
                 "{%0,%1,%2,%3}, {%4,%5,%6,%7}, {%8,%9}, {%0,%1,%2,%3};"
                 : "+f"(c[0]), "+f"(c[1]), "+f"(c[2]), "+f"(c[3])
                 : "r"(a0), "r"(a1), "r"(a2), "r"(a3), "r"(b0), "r"(b1));
}
__device__ __forceinline__ void cp16(uint32_t smem, const void* gmem) {
    asm volatile("cp.async.cg.shared.global [%0], [%1], 16;" :: "r"(smem), "l"(gmem));
}
#define CP_COMMIT() asm volatile("cp.async.commit_group;")
#define CP_WAIT(n)  asm volatile("cp.async.wait_group %0;" :: "n"(n))

// ---------------- small feature GEMM: g_xw[k][F] = in[N,KF] @ W[KF,F] ----------------
// Each thread produces one float4 of the output row.
template<int KF, int F>
__global__ __launch_bounds__(256) void feat_gemm(const float* __restrict__ in,
                                                 const float* __restrict__ W,
                                                 float* __restrict__ out) {
    __shared__ float Ws[KF * F];
    for (int i = threadIdx.x; i < KF * F; i += 256) Ws[i] = W[i];
    __syncthreads();
    int lin = blockIdx.x * 256 + threadIdx.x;
    if (lin >= N_NODES * F / 4) return;
    int row = lin / (F / 4);
    int j4  = (lin % (F / 4)) * 4;
    const float4* xr = reinterpret_cast<const float4*>(in + (size_t)row * KF);
    float a0 = 0.f, a1 = 0.f, a2 = 0.f, a3 = 0.f;
#pragma unroll 4
    for (int k4 = 0; k4 < KF / 4; k4++) {
        float4 xv = xr[k4];
#pragma unroll
        for (int e = 0; e < 4; e++) {
            float xs = (e == 0) ? xv.x : (e == 1) ? xv.y : (e == 2) ? xv.z : xv.w;
            float4 wv = *reinterpret_cast<const float4*>(&Ws[(k4 * 4 + e) * F + j4]);
            a0 += xs * wv.x; a1 += xs * wv.y; a2 += xs * wv.z; a3 += xs * wv.w;
        }
    }
    reinterpret_cast<float4*>(out)[lin] = make_float4(a0, a1, a2, a3);
}

// ---------------- transpose + bf16-pack: g_xwT[f][kpair] from g_xw[k][F] ----------------
template<int F>
__global__ __launch_bounds__(256) void xpose(const float* __restrict__ in,
                                             uint32_t* __restrict__ outT) {
    __shared__ float tile[64 * (F + 1)];
    const int tid = threadIdx.x;
    const int kb = blockIdx.x * 64;
#pragma unroll
    for (int i = 0; i < F / 16; i++) {
        int lin = tid + 256 * i;
        float4 v = reinterpret_cast<const float4*>(in + (size_t)kb * F)[lin];
        int k = (lin * 4) / F, f = (lin * 4) % F;
        tile[k * (F + 1) + f + 0] = v.x; tile[k * (F + 1) + f + 1] = v.y;
        tile[k * (F + 1) + f + 2] = v.z; tile[k * (F + 1) + f + 3] = v.w;
    }
    __syncthreads();
#pragma unroll
    for (int w = 0; w < F / 8; w++) {
        int lin = tid + 256 * w;
        int f = lin >> 5, j = lin & 31;
        outT[(size_t)f * (N_NODES / 2) + kb / 2 + j] =
            pack_bf16(tile[(2 * j) * (F + 1) + f], tile[(2 * j + 1) * (F + 1) + f]);
    }
}

// ---------------- shared compute fragment (natural layout, no swizzle) ----------------
template<int F, int NF2>
__device__ __forceinline__ void compute_tile(const uint4* __restrict__ As,
                                             const uint4* __restrict__ Bs,
                                             float c[2][NF2][4],
                                             int wx, int wy, int g, int t) {
#pragma unroll
    for (int mf = 0; mf < 2; mf++) {
        const int r0 = wx * 32 + mf * 16 + g;
        uint4 Alo = As[r0 * 4 + t];
        uint4 Ahi = As[(r0 + 8) * 4 + t];
#pragma unroll
        for (int nf = 0; nf < NF2; nf++) {
            const int n = wy * (F / 2) + nf * 8 + g;
            uint4 Bv = Bs[n * 4 + t];
            mma16(c[mf][nf], Alo.x, Ahi.x, Alo.y, Ahi.y, Bv.x, Bv.y);
            mma16(c[mf][nf], Alo.z, Ahi.z, Alo.w, Ahi.w, Bv.z, Bv.w);
        }
    }
}

template<int F, int NF2>
__device__ __forceinline__ void store_partials(float* __restrict__ part,
                                               float c[2][NF2][4],
                                               int rowBase, int wx, int wy, int g, int t) {
    float* pbase = part + (size_t)blockIdx.y * N_NODES * F;
#pragma unroll
    for (int mf = 0; mf < 2; mf++) {
        const int r0 = rowBase + wx * 32 + mf * 16 + g;
#pragma unroll
        for (int nf = 0; nf < NF2; nf++) {
            const int col = wy * (F / 2) + nf * 8 + 2 * t;
            *reinterpret_cast<float2*>(pbase + (size_t)r0 * F + col) =
                make_float2(c[mf][nf][0], c[mf][nf][1]);
            *reinterpret_cast<float2*>(pbase + (size_t)(r0 + 8) * F + col) =
                make_float2(c[mf][nf][2], c[mf][nf][3]);
        }
    }
}

// ---------------- layer 1: fp32 adj -> bf16 (RN) + GEMM + write g_adj16 ----------------
template<int F>
__global__ __launch_bounds__(256) void adj_gemm_cvt(const float* __restrict__ adj,
                                                    float* __restrict__ part) {
    constexpr int NF2 = F / 16;
    __shared__ __align__(16) uint4 As[2][BM * 4];
    __shared__ __align__(16) uint4 Bs[2][F * 4];

    const int tid = threadIdx.x;
    const int wid = tid >> 5, lane = tid & 31;
    const int g = lane >> 2, t = lane & 3;
    const int wx = wid >> 1, wy = wid & 1;
    const int rowBase = blockIdx.x * BM;
    const int k0 = blockIdx.y * KSPAN;

    float c[2][NF2][4];
#pragma unroll
    for (int mf = 0; mf < 2; mf++)
#pragma unroll
        for (int nf = 0; nf < NF2; nf++)
#pragma unroll
            for (int e = 0; e < 4; e++) c[mf][nf][e] = 0.f;

    // A staging map: 2 chunks/thread, chunk = 16B bf16 = 8 k values
    int a_r[2], a_c[2];
    const float4* a_src[2];
    uint4* a_dst[2];
#pragma unroll
    for (int i = 0; i < 2; i++) {
        int lin = tid + 256 * i;
        a_r[i] = lin >> 2; a_c[i] = lin & 3;
        a_src[i] = reinterpret_cast<const float4*>(
            adj + (size_t)(rowBase + a_r[i]) * N_NODES + k0 + 8 * a_c[i]);
        a_dst[i] = reinterpret_cast<uint4*>(
            g_adj16 + (size_t)(rowBase + a_r[i]) * N_NODES + k0 + 8 * a_c[i]);
    }
    // B staging: cp.async, 1 chunk/thread (active if tid < 4F)
    const bool bon = tid < 4 * F;
    const int b_f = tid >> 2, b_c = tid & 3;
    const uint32_t* b_src = g_xwT + (size_t)(bon ? b_f : 0) * (N_NODES / 2) + k0 / 2 + 4 * b_c;
    const uint32_t b_smem[2] = { smem_u32(&Bs[0][(b_f * 4 + b_c)]), smem_u32(&Bs[1][(b_f * 4 + b_c)]) };

    float4 rA[2][2];
    // prologue: A tile 0 regs, B tile 0 cp.async
#pragma unroll
    for (int i = 0; i < 2; i++) { rA[i][0] = a_src[i][0]; rA[i][1] = a_src[i][1]; }
    if (bon) cp16(b_smem[0], b_src);
    CP_COMMIT();

#pragma unroll 1
    for (int ti = 0; ti < NKT; ti++) {
        const int buf = ti & 1;
        // stage A ti (pack + STS.128 + STG.128 bf16 copy)
#pragma unroll
        for (int i = 0; i < 2; i++) {
            uint4 p = make_uint4(pack_bf16(rA[i][0].x, rA[i][0].y), pack_bf16(rA[i][0].z, rA[i][0].w),
                                 pack_bf16(rA[i][1].x, rA[i][1].y), pack_bf16(rA[i][1].z, rA[i][1].w));
            As[buf][a_r[i] * 4 + a_c[i]] = p;
            a_dst[i][(size_t)ti * (BK / 8)] = p;
        }
        // prefetch A ti+1
        if (ti + 1 < NKT) {
#pragma unroll
            for (int i = 0; i < 2; i++) {
                const float4* s = a_src[i] + (size_t)(ti + 1) * (BK / 4);
                rA[i][0] = s[0]; rA[i][1] = s[1];
            }
        }
        CP_WAIT(0);              // B ti arrived
        __syncthreads();         // all staged / prev compute done
        if (ti + 1 < NKT) {      // issue B ti+1 (buffer was fully read before this sync)
            if (bon) cp16(b_smem[buf ^ 1], b_src + (ti + 1) * (BK / 2));
            CP_COMMIT();
        }
        compute_tile<F, NF2>(As[buf], Bs[buf], c, wx, wy, g, t);
    }
    store_partials<F, NF2>(part, c, rowBase, wx, wy, g, t);
}

// ---------------- layers 2/3: bf16 adj, full cp.async 3-stage pipeline ----------------
template<int F>
__global__ __launch_bounds__(256) void adj_gemm_cp(float* __restrict__ part) {
    constexpr int NF2 = F / 16;
    __shared__ __align__(16) uint4 As[3][BM * 4];
    __shared__ __align__(16) uint4 Bs[3][F * 4];

    const int tid = threadIdx.x;
    const int wid = tid >> 5, lane = tid & 31;
    const int g = lane >> 2, t = lane & 3;
    const int wx = wid >> 1, wy = wid & 1;
    const int rowBase = blockIdx.x * BM;
    const int k0 = blockIdx.y * KSPAN;

    float c[2][NF2][4];
#pragma unroll
    for (int mf = 0; mf < 2; mf++)
#pragma unroll
        for (int nf = 0; nf < NF2; nf++)
#pragma unroll
            for (int e = 0; e < 4; e++) c[mf][nf][e] = 0.f;

    // A: 2 chunks/thread
    int a_r[2], a_c[2];
    const __nv_bfloat16* a_src[2];
#pragma unroll
    for (int i = 0; i < 2; i++) {
        int lin = tid + 256 * i;
        a_r[i] = lin >> 2; a_c[i] = lin & 3;
        a_src[i] = g_adj16 + (size_t)(rowBase + a_r[i]) * N_NODES + k0 + 8 * a_c[i];
    }
    // B: 1 chunk/thread
    const bool bon = tid < 4 * F;
    const int b_f = tid >> 2, b_c = tid & 3;
    const uint32_t* b_src = g_xwT + (size_t)(bon ? b_f : 0) * (N_NODES / 2) + k0 / 2 + 4 * b_c;

    uint32_t a_sm[2][3], b_sm[3];
#pragma unroll
    for (int s = 0; s < 3; s++) {
#pragma unroll
        for (int i = 0; i < 2; i++) a_sm[i][s] = smem_u32(&As[s][a_r[i] * 4 + a_c[i]]);
        b_sm[s] = smem_u32(&Bs[s][b_f * 4 + b_c]);
    }

    auto issue = [&](int ti, int s) {
#pragma unroll
        for (int i = 0; i < 2; i++) cp16(a_sm[i][s], a_src[i] + (size_t)ti * BK);
        if (bon) cp16(b_sm[s], b_src + ti * (BK / 2));
        CP_COMMIT();
    };

    issue(0, 0);
    issue(1, 1);

#pragma unroll 1
    for (int ti = 0; ti < NKT; ti++) {
        const int s = ti % 3;
        if (ti + 1 < NKT) { CP_WAIT(1); } else { CP_WAIT(0); }
        __syncthreads();
        if (ti + 2 < NKT) issue(ti + 2, (ti + 2) % 3);
        compute_tile<F, NF2>(As[s], Bs[s], c, wx, wy, g, t);
    }
    store_partials<F, NF2>(part, c, rowBase, wx, wy, g, t);
}

// ---------------- combine split-K partials: h = relu(sum_sk part + b) ----------------
template<int F>
__global__ __launch_bounds__(256) void combine_h(const float* __restrict__ part,
                                                 const float* __restrict__ bias,
                                                 float* __restrict__ h) {
    int idx = blockIdx.x * 256 + threadIdx.x;
    if (idx >= N_NODES * F / 4) return;
    float4 s = make_float4(0.f, 0.f, 0.f, 0.f);
#pragma unroll
    for (int sk = 0; sk < SPLITK; sk++) {
        float4 v = reinterpret_cast<const float4*>(part)[(size_t)sk * (N_NODES * F / 4) + idx];
        s.x += v.x; s.y += v.y; s.z += v.z; s.w += v.w;
    }
    int f = (idx * 4) % F;
    s.x = fmaxf(s.x + bias[f + 0], 0.f);
    s.y = fmaxf(s.y + bias[f + 1], 0.f);
    s.z = fmaxf(s.z + bias[f + 2], 0.f);
    s.w = fmaxf(s.w + bias[f + 3], 0.f);
    reinterpret_cast<float4*>(h)[idx] = s;
}

// ---------------- layer-3 combine + deterministic column reduction (F=64) ----------------
__global__ __launch_bounds__(256) void combine_reduce(const float* __restrict__ part,
                                                      const float* __restrict__ bias,
                                                      float* __restrict__ colsum) {
    __shared__ float red[4][64];
    const int tid = threadIdx.x;
    const int c = tid & 63, rg = tid >> 6;
    const int rowBase = blockIdx.x * 64;
    const float b = bias[c];
    float s = 0.f;
#pragma unroll 4
    for (int i = 0; i < 16; i++) {
        const int row = rowBase + rg + 4 * i;
        float v = 0.f;
#pragma unroll
        for (int sk = 0; sk < SPLITK; sk++)
            v += part[((size_t)sk * N_NODES + row) * 64 + c];
        s += fmaxf(v + b, 0.f);
    }
    red[rg][c] = s;
    __syncthreads();
    if (rg == 0)
        colsum[blockIdx.x * 64 + c] = red[0][c] + red[1][c] + red[2][c] + red[3][c];
}

// ---------------- readout + MLP head + softmax ----------------
__global__ void head_kernel(const float* __restrict__ colsum,
                            const float* __restrict__ fcW1, const float* __restrict__ fcb1,
                            const float* __restrict__ fcW2, const float* __restrict__ fcb2,
                            float* __restrict__ out) {
    __shared__ float mean_s[64];
    __shared__ float z1_s[32];
    int t = threadIdx.x;  // 64 threads
    float s = 0.f;
    for (int b = 0; b < 256; b++) s += colsum[b * 64 + t];
    mean_s[t] = s * (1.0f / N_NODES);
    __syncthreads();
    if (t < 32) {
        float a = 0.f;
#pragma unroll
        for (int c = 0; c < 64; c++) a += mean_s[c] * fcW1[c * 32 + t];
        z1_s[t] = fmaxf(a + fcb1[t], 0.f);
    }
    __syncthreads();
    if (t == 0) {
        float z0 = fcb2[0], z1 = fcb2[1];
#pragma unroll
        for (int j = 0; j < 32; j++) {
            z0 += z1_s[j] * fcW2[j * 2 + 0];
            z1 += z1_s[j] * fcW2[j * 2 + 1];
        }
        float m  = fmaxf(z0, z1);
        float e0 = expf(z0 - m), e1 = expf(z1 - m);
        float inv = 1.0f / (e0 + e1);
        out[0] = e0 * inv;
        out[1] = e1 * inv;
    }
}

// ---------------- launch ----------------
extern "C" void kernel_launch(void* const* d_in, const int* in_sizes, int n_in,
                              void* d_out, int out_size) {
    const float* x    = (const float*)d_in[0];
    const float* adj  = (const float*)d_in[1];
    // d_in[2] = idx_map (unused by the reference)
    const float* W1   = (const float*)d_in[3];
    const float* b1   = (const float*)d_in[4];
    const float* W2   = (const float*)d_in[5];
    const float* b2   = (const float*)d_in[6];
    const float* W3   = (const float*)d_in[7];
    const float* b3   = (const float*)d_in[8];
    const float* fcW1 = (const float*)d_in[9];
    const float* fcb1 = (const float*)d_in[10];
    const float* fcW2 = (const float*)d_in[11];
    const float* fcb2 = (const float*)d_in[12];
    float* out = (float*)d_out;

    float *xw, *h, *part, *colsum;
    uint32_t* xwT;
    cudaGetSymbolAddress((void**)&xw, g_xw);
    cudaGetSymbolAddress((void**)&xwT, g_xwT);
    cudaGetSymbolAddress((void**)&h, g_h);
    cudaGetSymbolAddress((void**)&part, g_part);
    cudaGetSymbolAddress((void**)&colsum, g_colsum);

    dim3 agrid(N_NODES / BM, SPLITK);

    feat_gemm<128, 32><<<N_NODES * 32 / 4 / 256, 256>>>(x, W1, xw);
    xpose<32><<<N_NODES / 64, 256>>>(xw, xwT);
    adj_gemm_cvt<32><<<agrid, 256>>>(adj, part);
    combine_h<32><<<(N_NODES * 32 / 4 + 255) / 256, 256>>>(part, b1, h);

    feat_gemm<32, 48><<<N_NODES * 48 / 4 / 256, 256>>>(h, W2, xw);
    xpose<48><<<N_NODES / 64, 256>>>(xw, xwT);
    adj_gemm_cp<48><<<agrid, 256>>>(part);
    combine_h<48><<<(N_NODES * 48 / 4 + 255) / 256, 256>>>(part, b2, h);

    feat_gemm<48, 64><<<N_NODES * 64 / 4 / 256, 256>>>(h, W3, xw);
    xpose<64><<<N_NODES / 64, 256>>>(xw, xwT);
    adj_gemm_cp<64><<<agrid, 256>>>(part);
    combine_reduce<<<256, 256>>>(part, b3, colsum);

    head_kernel<<<1, 64>>>(colsum, fcW1, fcb1, fcW2, fcb2, out);
}